// round 5
// baseline (speedup 1.0000x reference)
#include <cuda_runtime.h>
#include <float.h>

// Problem constants (fixed: B=4, M=1024, N=32768)
#define BB 4
#define MM 1024
#define NN 32768
#define NPAIRS (NN / 2)        // 16384 point-pairs per batch
#define NCHUNK 148             // chunks per batch; 148*4 = 592 blocks = exactly 4/SM, 1 wave
#define TILE 111               // ceil(16384/148); tail clamped at copy time
#define KT 8                   // keypoints per thread
#define NTHREADS 128           // 128 * 8 = 1024 = all keypoints per block
#define NROWS (BB * MM)        // 4096

typedef unsigned long long u64;

// Row-min table, ordered-uint encoded (larger key == smaller v). No cudaMalloc allowed.
__device__ unsigned g_rowmin[NROWS];

// ---- packed f32x2 helpers (Blackwell FFMA2 path) ----
__device__ __forceinline__ u64 fma2(u64 a, u64 b, u64 c) {
    u64 d; asm("fma.rn.f32x2 %0, %1, %2, %3;" : "=l"(d) : "l"(a), "l"(b), "l"(c));
    return d;
}
__device__ __forceinline__ u64 mul2(u64 a, u64 b) {
    u64 d; asm("mul.rn.f32x2 %0, %1, %2;" : "=l"(d) : "l"(a), "l"(b));
    return d;
}
__device__ __forceinline__ u64 dup2(float x) {
    u64 d; asm("mov.b64 %0, {%1, %1};" : "=l"(d) : "f"(x));
    return d;
}
__device__ __forceinline__ void unpack2(u64 v, float& lo, float& hi) {
    asm("mov.b64 {%0, %1}, %2;" : "=f"(lo), "=f"(hi) : "l"(v));
}

// Monotone DECREASING float->uint key: x1 < x2  <=>  key(x1) > key(x2).
// key = ~flip(u), flip(u) = (u>>31) ? ~u : u|0x80000000. Init 0 loses to all reals.
__device__ __forceinline__ unsigned enc_min(float v) {
    unsigned u = __float_as_uint(v);
    unsigned flip = ((int)u < 0) ? ~u : (u | 0x80000000u);
    return ~flip;
}
__device__ __forceinline__ float dec_min(unsigned key) {
    unsigned flip = ~key;
    unsigned u = (flip & 0x80000000u) ? (flip ^ 0x80000000u) : ~flip;
    return __uint_as_float(u);
}

// --- Kernel 0: reset the row-min table (must precede min_kernel each replay) ---
__global__ void init_kernel() {
    ((uint4*)g_rowmin)[blockIdx.x * 256 + threadIdx.x] = make_uint4(0, 0, 0, 0);
}

// --- Kernel 1: per (chunk, b) block: min over chunk's points for all 1024 keypoints.
// v = |p|^2 - 2 k.p  (d2 = |k|^2 + min v applied in the final kernel).
__global__ void __launch_bounds__(NTHREADS, 4)
min_kernel(const float* __restrict__ kpt, const float* __restrict__ pc) {
    const int chunk = blockIdx.x;
    const int b     = blockIdx.y;
    const int t     = threadIdx.x;
    const int m0    = t * KT;

    // smem: per pair i: s_pts[2i]={x2,y2}, s_pts[2i+1]={z2,pp}  (two LDS.128 per iter)
    __shared__ ulonglong2 s_pts[2 * TILE];

    // Copy phase: stage this chunk's point-pairs + packed |p|^2 (computed once).
    if (t < TILE) {
        int q = min(chunk * TILE + t, NPAIRS - 1);  // tail clamp: dup pair is a min no-op
        const float* pcb = pc + (size_t)b * 3 * NN;
        u64 x2 = ((const u64*)pcb)[q];
        u64 y2 = ((const u64*)(pcb + NN))[q];
        u64 z2 = ((const u64*)(pcb + 2 * NN))[q];
        u64 pp = fma2(z2, z2, fma2(y2, y2, mul2(x2, x2)));  // (|p0|^2, |p1|^2)
        ulonglong2 a, c;
        a.x = x2; a.y = y2;
        c.x = z2; c.y = pp;
        s_pts[2 * t]     = a;
        s_pts[2 * t + 1] = c;
    }

    // Per-thread keypoints, scaled by -2, duplicated into both f32x2 halves (hoisted).
    const float* kb = kpt + (size_t)b * 3 * MM;
    u64 knx[KT], kny[KT], knz[KT];
    float mnl[KT], mnh[KT];
#pragma unroll
    for (int j = 0; j < KT; j++) {
        knx[j] = dup2(-2.0f * kb[m0 + j]);
        kny[j] = dup2(-2.0f * kb[MM + m0 + j]);
        knz[j] = dup2(-2.0f * kb[2 * MM + m0 + j]);
        mnl[j] = FLT_MAX;
        mnh[j] = FLT_MAX;
    }
    __syncthreads();

    // Main loop: pure compute against smem (broadcast LDS, conflict-free).
#pragma unroll 3
    for (int i = 0; i < TILE; i++) {
        ulonglong2 a = s_pts[2 * i];      // (x2, y2)
        ulonglong2 c = s_pts[2 * i + 1];  // (z2, pp)
#pragma unroll
        for (int j = 0; j < KT; j++) {
            u64 v = fma2(knx[j], a.x, fma2(kny[j], a.y, fma2(knz[j], c.x, c.y)));
            float lo, hi;
            unpack2(v, lo, hi);  // register-pair aliasing, no real MOVs
            mnl[j] = fminf(mnl[j], lo);
            mnh[j] = fminf(mnh[j], hi);
        }
    }

    // Fire-and-forget REDG.MAX per keypoint (order-independent => deterministic).
    unsigned* rp = g_rowmin + b * MM + m0;
#pragma unroll
    for (int j = 0; j < KT; j++)
        atomicMax(rp + j, enc_min(fminf(mnl[j], mnh[j])));
}

// --- Kernel 2: single block: decode row mins, add |k|^2, sqrt, mean ---
__global__ void __launch_bounds__(1024)
final_kernel(const float* __restrict__ kpt, float* __restrict__ out) {
    const int t = threadIdx.x;
    float sum = 0.0f;
#pragma unroll
    for (int rr = 0; rr < NROWS / 1024; rr++) {
        int r = rr * 1024 + t;
        float v = dec_min(g_rowmin[r]);
        int b = r >> 10, m = r & (MM - 1);
        const float* kb = kpt + (size_t)b * 3 * MM;
        float x = kb[m], y = kb[MM + m], z = kb[2 * MM + m];
        sum += sqrtf(fmaxf(v + (x * x + y * y + z * z), 0.0f));
    }
    __shared__ float ss[1024];
    ss[t] = sum;
    __syncthreads();
#pragma unroll
    for (int s = 512; s >= 32; s >>= 1) {
        if (t < s) ss[t] += ss[t + s];
        __syncthreads();
    }
    if (t < 32) {
        float v = ss[t];
#pragma unroll
        for (int off = 16; off; off >>= 1) v += __shfl_xor_sync(0xffffffffu, v, off);
        if (t == 0) *out = v * (1.0f / (float)NROWS);
    }
}

extern "C" void kernel_launch(void* const* d_in, const int* in_sizes, int n_in,
                              void* d_out, int out_size) {
    const float* keypoints = (const float*)d_in[0];  // [B,3,M]
    const float* pc        = (const float*)d_in[1];  // [B,3,N]
    float* out             = (float*)d_out;          // scalar

    (void)in_sizes; (void)n_in; (void)out_size;

    init_kernel<<<NROWS / 4 / 256, 256>>>();
    dim3 grid(NCHUNK, BB);
    min_kernel<<<grid, NTHREADS>>>(keypoints, pc);
    final_kernel<<<1, 1024>>>(keypoints, out);
}